// round 2
// baseline (speedup 1.0000x reference)
#include <cuda_runtime.h>
#include <cuda_bf16.h>
#include <math.h>

#define IMG_H 512
#define IMG_W 640
#define HW (IMG_H * IMG_W)            // 327680
#define FXc 500.0f
#define FYc 500.0f
#define CXc 320.0f
#define CYc 256.0f

#define SCAN_BLK 1024
#define NSCAN_BLOCKS (HW / SCAN_BLK)  // 320

#define NPAD 524288                   // 2^19 >= n_valid (~316k), power of two
#define NCHUNK 256                    // NPAD / 2048

// ---------------- device scratch ----------------
__device__ unsigned int g_cnt[HW];
__device__ unsigned int g_off[HW];
__device__ unsigned int g_woff[HW];
__device__ unsigned int g_bsum[NSCAN_BLOCKS];
__device__ unsigned int g_boff[NSCAN_BLOCKS];

__device__ float g_z[NPAD];
__device__ float g_w[NPAD];
__device__ float4 g_feat[NPAD];
__device__ unsigned int g_idx[NPAD];

__device__ float g_x[NPAD];    // lg = log1p(-w) at sorted positions (zero padded)
__device__ float g_S[NPAD];    // inclusive scan with replicated assoc-scan rounding
__device__ float g_L11[NCHUNK];
__device__ float g_S11[NCHUNK];

// ---------------- projection (bit-exact vs XLA: no FMA contraction) ----------------
__device__ __forceinline__ bool project_point(
    const float* __restrict__ means, const float* __restrict__ pose,
    int i, float& z_out, int& pid_out)
{
    float m0 = means[3 * i + 0];
    float m1 = means[3 * i + 1];
    float m2 = means[3 * i + 2];
    // pose is identity in this problem: these are exact regardless of order.
    float pc0 = m0 * pose[0] + m1 * pose[1] + m2 * pose[2]  + pose[3];
    float pc1 = m0 * pose[4] + m1 * pose[5] + m2 * pose[6]  + pose[7];
    float z   = m0 * pose[8] + m1 * pose[9] + m2 * pose[10] + pose[11];
    // x = pc0/z * FX + CX with IEEE rn div/mul/add, NO fma (matches XLA)
    float x = __fadd_rn(__fmul_rn(__fdiv_rn(pc0, z), FXc), CXc);
    float y = __fadd_rn(__fmul_rn(__fdiv_rn(pc1, z), FYc), CYc);
    bool valid = (x >= 0.0f) && (x < (float)IMG_W) &&
                 (y >= 0.0f) && (y < (float)IMG_H) && (z > 0.0f);
    if (valid) {
        int xi = (int)floorf(x);
        int yi = (int)floorf(y);
        pid_out = yi * IMG_W + xi;
        z_out = z;
    }
    return valid;
}

// ---------------- pass 1: count ----------------
__global__ void count_kernel(const float* __restrict__ means,
                             const float* __restrict__ pose, int n)
{
    int i = blockIdx.x * blockDim.x + threadIdx.x;
    if (i >= n) return;
    float z; int pid;
    if (project_point(means, pose, i, z, pid))
        atomicAdd(&g_cnt[pid], 1u);
}

// ---------------- offset scan (counting sort) ----------------
__global__ void scan_block_kernel()
{
    __shared__ unsigned int sh[SCAN_BLK];
    int t = threadIdx.x;
    int gi = blockIdx.x * SCAN_BLK + t;
    unsigned int v = g_cnt[gi];
    sh[t] = v;
    __syncthreads();
#pragma unroll
    for (int d = 1; d < SCAN_BLK; d <<= 1) {
        unsigned int add = (t >= d) ? sh[t - d] : 0u;
        __syncthreads();
        sh[t] += add;
        __syncthreads();
    }
    g_off[gi] = sh[t] - v;
    if (t == SCAN_BLK - 1) g_bsum[blockIdx.x] = sh[t];
}

__global__ void scan_top_kernel()
{
    __shared__ unsigned int sh[512];
    int t = threadIdx.x;
    unsigned int v = (t < NSCAN_BLOCKS) ? g_bsum[t] : 0u;
    sh[t] = v;
    __syncthreads();
#pragma unroll
    for (int d = 1; d < 512; d <<= 1) {
        unsigned int add = (t >= d) ? sh[t - d] : 0u;
        __syncthreads();
        sh[t] += add;
        __syncthreads();
    }
    if (t < NSCAN_BLOCKS) g_boff[t] = sh[t] - v;
}

__global__ void scan_add_kernel()
{
    int t = threadIdx.x;
    int gi = blockIdx.x * SCAN_BLK + t;
    unsigned int o = g_off[gi] + g_boff[blockIdx.x];
    g_off[gi] = o;
    g_woff[gi] = o;
}

// ---------------- pass 2: scatter ----------------
__global__ void scatter_kernel(const float* __restrict__ means,
                               const float* __restrict__ opac,
                               const float* __restrict__ feats,
                               const float* __restrict__ pose, int n)
{
    int i = blockIdx.x * blockDim.x + threadIdx.x;
    if (i >= n) return;
    float z; int pid;
    if (project_point(means, pose, i, z, pid)) {
        unsigned int pos = atomicAdd(&g_woff[pid], 1u);
        if (pos < NPAD) {
            g_z[pos] = z;
            g_w[pos] = opac[i];
            g_feat[pos] = make_float4(feats[3 * i + 0], feats[3 * i + 1],
                                      feats[3 * i + 2], 0.0f);
            g_idx[pos] = (unsigned int)i;
        }
    }
}

// ---------------- per-pixel sort (z desc, idx asc) + emit lg ----------------
__global__ void sortemit_kernel()
{
    int p = blockIdx.x * blockDim.x + threadIdx.x;
    if (p >= HW) return;
    unsigned int s = g_off[p];
    unsigned int k = g_cnt[p];
    if (k == 0) return;
    // selection sort on global arrays (k ~ 1 avg, <= ~12)
    for (unsigned int i = 0; i < k; i++) {
        unsigned int best = i;
        float bz = g_z[s + i];
        unsigned int bi = g_idx[s + i];
        for (unsigned int j = i + 1; j < k; j++) {
            float zj = g_z[s + j];
            unsigned int ij = g_idx[s + j];
            if (zj > bz || (zj == bz && ij < bi)) { best = j; bz = zj; bi = ij; }
        }
        if (best != i) {
            float tz = g_z[s + i];     g_z[s + i] = g_z[s + best];     g_z[s + best] = tz;
            float tw = g_w[s + i];     g_w[s + i] = g_w[s + best];     g_w[s + best] = tw;
            float4 tf = g_feat[s + i]; g_feat[s + i] = g_feat[s + best]; g_feat[s + best] = tf;
            unsigned int ti = g_idx[s + i]; g_idx[s + i] = g_idx[s + best]; g_idx[s + best] = ti;
        }
        g_x[s + i] = log1pf(-g_w[s + i]);
    }
}

// ---------------- scan A: per-chunk pairwise tree sum (levels 1..11) ----------------
__global__ void scan_down_kernel()
{
    __shared__ float sh[2048];
    int t = threadIdx.x;               // 1024
    int base = blockIdx.x * 2048;
    sh[t] = g_x[base + t];
    sh[t + 1024] = g_x[base + t + 1024];
    __syncthreads();
    for (int size = 1024; size >= 1; size >>= 1) {
        float v = 0.0f;
        if (t < size) v = sh[2 * t] + sh[2 * t + 1];
        __syncthreads();
        if (t < size) sh[t] = v;
        __syncthreads();
    }
    if (t == 0) g_L11[blockIdx.x] = sh[0];
}

// ---------------- scan B: levels 12..19 + S11 (single block) ----------------
__global__ void scan_mid_kernel()
{
    __shared__ float Lv[511];
    __shared__ float Sv[511];
    int t = threadIdx.x;               // 256
    Lv[t] = g_L11[t];
    __syncthreads();
    int off = 0, size = 256;
    for (int d = 0; d < 8; d++) {
        int noff = off + size, nsz = size >> 1;
        if (t < nsz) Lv[noff + t] = Lv[off + 2 * t] + Lv[off + 2 * t + 1];
        __syncthreads();
        off = noff; size = nsz;
    }
    // off = 510 (top, size 1)
    if (t == 0) Sv[510] = Lv[510];
    __syncthreads();
    for (int d = 0; d < 8; d++) {
        int sz = 2 << d;               // 2,4,...,256
        off -= sz;
        int poff = off + sz;           // level above
        if (t < sz) {
            float v;
            if (t == 0)      v = Lv[off];
            else if (t & 1)  v = Sv[poff + ((t - 1) >> 1)];
            else             v = Sv[poff + (t >> 1) - 1] + Lv[off + t];
            Sv[off + t] = v;
        }
        __syncthreads();
    }
    g_S11[t] = Sv[t];
}

// ---------------- scan C: up-sweep, writes S (level 0) ----------------
__global__ void scan_up_kernel()
{
    __shared__ float Lb[4094];
    __shared__ float Sa[2048];
    __shared__ float Sb[1024];
    int t = threadIdx.x;               // 1024
    int b = blockIdx.x;
    int base = b * 2048;
    Lb[t] = g_x[base + t];
    Lb[t + 1024] = g_x[base + t + 1024];
    __syncthreads();
    // rebuild local levels 1..10 (identical adjacent-pair rounding)
    int off = 0, size = 2048;
    for (int d = 1; d <= 10; d++) {
        int noff = off + size, nsz = size >> 1;
        for (int j = t; j < nsz; j += 1024)
            Lb[noff + j] = Lb[off + 2 * j] + Lb[off + 2 * j + 1];
        __syncthreads();
        off = noff; size = nsz;
    }
    // off = 4092 = level 10 (size 2)
    float bound = (b > 0) ? g_S11[b - 1] : 0.0f;
    if (t == 0) {
        Sa[0] = (b == 0) ? Lb[off] : bound + Lb[off];
        Sa[1] = g_S11[b];
    }
    __syncthreads();
    for (int d = 9; d >= 0; d--) {
        int sz = 2048 >> d;
        off -= sz;
        float* Sprev = (d & 1) ? Sa : Sb;  // level d+1 store
        float* Scur  = (d & 1) ? Sb : Sa;  // level d store (d even -> Sa)
        for (int j = t; j < sz; j += 1024) {
            float v;
            if (j == 0)      v = (b == 0) ? Lb[off] : bound + Lb[off];
            else if (j & 1)  v = Sprev[(j - 1) >> 1];
            else             v = Sprev[(j >> 1) - 1] + Lb[off + j];
            Scur[j] = v;
        }
        __syncthreads();
    }
    g_S[base + t] = Sa[t];
    g_S[base + t + 1024] = Sa[t + 1024];
}

// ---------------- render ----------------
__global__ void render_kernel(float* __restrict__ out)
{
    int p = blockIdx.x * blockDim.x + threadIdx.x;
    if (p >= HW) return;
    unsigned int s = g_off[p];
    unsigned int k = g_cnt[p];

    float img0 = 0.0f, img1 = 0.0f, img2 = 0.0f;
    float dep = 0.0f;
    float Lsum = 0.0f;

    float c_end = (k > 0) ? g_S[s + k - 1] : 0.0f;
    for (unsigned int i = 0; i < k; i++) {
        float T = expf(c_end - g_S[s + i]);
        float w = g_w[s + i];
        float contrib = w * T;
        float4 f = g_feat[s + i];
        img0 += contrib * f.x;
        img1 += contrib * f.y;
        img2 += contrib * f.z;
        dep  += contrib * g_z[s + i];
        Lsum += g_x[s + i];
    }

    out[0 * HW + p] = img0;
    out[1 * HW + p] = img1;
    out[2 * HW + p] = img2;
    out[3 * HW + p] = dep;
    out[4 * HW + p] = 1.0f - expf(Lsum);
}

// ---------------- launch ----------------
extern "C" void kernel_launch(void* const* d_in, const int* in_sizes, int n_in,
                              void* d_out, int out_size)
{
    const float* means = (const float*)d_in[0];
    const float* opac  = (const float*)d_in[1];
    const float* feats = (const float*)d_in[2];
    const float* pose  = (const float*)d_in[3];
    float* out = (float*)d_out;

    int n = in_sizes[0] / 3;

    void* cnt_addr = nullptr; cudaGetSymbolAddress(&cnt_addr, g_cnt);
    void* x_addr   = nullptr; cudaGetSymbolAddress(&x_addr, g_x);
    cudaMemsetAsync(cnt_addr, 0, HW * sizeof(unsigned int), 0);
    cudaMemsetAsync(x_addr, 0, NPAD * sizeof(float), 0);

    int tpb = 256;
    int nblk = (n + tpb - 1) / tpb;

    count_kernel<<<nblk, tpb>>>(means, pose, n);
    scan_block_kernel<<<NSCAN_BLOCKS, SCAN_BLK>>>();
    scan_top_kernel<<<1, 512>>>();
    scan_add_kernel<<<NSCAN_BLOCKS, SCAN_BLK>>>();
    scatter_kernel<<<nblk, tpb>>>(means, opac, feats, pose, n);
    sortemit_kernel<<<(HW + tpb - 1) / tpb, tpb>>>();
    scan_down_kernel<<<NCHUNK, 1024>>>();
    scan_mid_kernel<<<1, 256>>>();
    scan_up_kernel<<<NCHUNK, 1024>>>();
    render_kernel<<<(HW + tpb - 1) / tpb, tpb>>>(out);
}